// round 15
// baseline (speedup 1.0000x reference)
#include <cuda_runtime.h>
#include <cuda_bf16.h>
#include <cstdint>
#include <cstddef>
#include <math.h>

// Problem constants
#define Bn 64
#define Hn 1024
#define Vn 8192
#define G4 4096
#define TMAX 128
#define NPART 128          // step-gemm grid = 128 v-tiles of 64

typedef unsigned long long u64;
typedef unsigned int u32;

// ---------------- persistent device state (legal scratch) ----------------
__device__ __align__(128) float g_gates[Bn*G4];
__device__ __align__(128) float g_c[Bn*Hn];
__device__ float g_pval[Bn*NPART];
__device__ int   g_pidx[Bn*NPART];
__device__ __align__(128) float g_WihT[(size_t)Vn*G4];        // W_ih^T for coalesced column gather
__device__ __align__(128) float g_stage[(size_t)TMAX*Bn*Vn];  // step outputs, t-major
// bf16x3 limbs of W_fc (V x H each) and of h (B x H each)
__device__ __align__(128) __nv_bfloat16 g_W0[(size_t)Vn*Hn];
__device__ __align__(128) __nv_bfloat16 g_W1[(size_t)Vn*Hn];
__device__ __align__(128) __nv_bfloat16 g_W2[(size_t)Vn*Hn];
__device__ __align__(128) __nv_bfloat16 g_h0[Bn*Hn];
__device__ __align__(128) __nv_bfloat16 g_h1[Bn*Hn];
__device__ __align__(128) __nv_bfloat16 g_h2[Bn*Hn];

__device__ __forceinline__ float sigm(float x){ return 1.0f/(1.0f+expf(-x)); }

__device__ __forceinline__ u32 smem_u32(const void* p){
    u32 a;
    asm("{ .reg .u64 t; cvta.to.shared.u64 t, %1; cvt.u32.u64 %0, t; }" : "=r"(a) : "l"(p));
    return a;
}
#define SW128(o) ((o) ^ (((o)>>3)&0x70))

// ---- baseline-PTX ops (all sm_80-era: safe on compute_103) ----
#define LDSM_X4(r, a) \
    asm volatile("ldmatrix.sync.aligned.m8n8.x4.shared.b16 {%0,%1,%2,%3}, [%4];" \
        : "=r"((r)[0]),"=r"((r)[1]),"=r"((r)[2]),"=r"((r)[3]) : "r"(a))
#define MMA16816(d, a, b0v, b1v) \
    asm volatile("mma.sync.aligned.m16n8k16.row.col.f32.bf16.bf16.f32 " \
        "{%0,%1,%2,%3}, {%4,%5,%6,%7}, {%8,%9}, {%0,%1,%2,%3};" \
        : "+f"((d)[0]),"+f"((d)[1]),"+f"((d)[2]),"+f"((d)[3]) \
        : "r"((a)[0]),"r"((a)[1]),"r"((a)[2]),"r"((a)[3]), "r"(b0v),"r"(b1v))
#define CP16(dst, src) \
    asm volatile("cp.async.cg.shared.global [%0], [%1], 16;" :: "r"(dst), "l"(src))
#define CP_COMMIT() asm volatile("cp.async.commit_group;" ::: "memory")
#define CP_WAIT(N)  asm volatile("cp.async.wait_group %0;" :: "n"(N) : "memory")

// ---------------- one-time prep: W_ih transpose + W_fc limb split ----------------
#define SPLIT_BLOCKS 8192
__global__ void __launch_bounds__(256)
prep_weights(const float* __restrict__ Wih, const float* __restrict__ Wfc)
{
    if (blockIdx.x < SPLIT_BLOCKS){
        // W_fc (fp32) -> 3 bf16 limbs, 4 floats/thread
        size_t base = ((size_t)blockIdx.x*256 + threadIdx.x)*4;
        float4 a = *(const float4*)(Wfc + base);
        float v[4] = {a.x, a.y, a.z, a.w};
        unsigned short p0[4], p1[4], p2[4];
        #pragma unroll
        for (int i=0;i<4;i++){
            __nv_bfloat16 b0 = __float2bfloat16(v[i]);
            float r = v[i] - __bfloat162float(b0);
            __nv_bfloat16 b1 = __float2bfloat16(r);
            r -= __bfloat162float(b1);
            __nv_bfloat16 b2 = __float2bfloat16(r);
            p0[i] = *(unsigned short*)&b0;
            p1[i] = *(unsigned short*)&b1;
            p2[i] = *(unsigned short*)&b2;
        }
        u64 w0 = (u64)p0[0] | ((u64)p0[1]<<16) | ((u64)p0[2]<<32) | ((u64)p0[3]<<48);
        u64 w1 = (u64)p1[0] | ((u64)p1[1]<<16) | ((u64)p1[2]<<32) | ((u64)p1[3]<<48);
        u64 w2 = (u64)p2[0] | ((u64)p2[1]<<16) | ((u64)p2[2]<<32) | ((u64)p2[3]<<48);
        ((u64*)g_W0)[base/4] = w0;
        ((u64*)g_W1)[base/4] = w1;
        ((u64*)g_W2)[base/4] = w2;
    } else {
        // W_ih (4H x V) -> g_WihT (V x 4H), tiled transpose
        __shared__ float tile[32][33];
        const int bx = blockIdx.x - SPLIT_BLOCKS;
        const int v0 = (bx & 255) * 32;       // 256 v-tiles
        const int g0 = (bx >> 8) * 32;        // 128 g-tiles
        const int tx = threadIdx.x & 31, ty = threadIdx.x >> 5;   // 32 x 8
        #pragma unroll
        for (int i = 0; i < 32; i += 8)
            tile[ty+i][tx] = Wih[(size_t)(g0+ty+i)*Vn + (v0+tx)];
        __syncthreads();
        #pragma unroll
        for (int i = 0; i < 32; i += 8)
            g_WihT[(size_t)(v0+ty+i)*G4 + (g0+tx)] = tile[tx][ty+i];
    }
}

// ---------------- init: gates0 = h0 @ W_hh^T + b_ih + b_hh (SIMT, runs once) ----------------
#define NKK 32
#define MR  65
#define STAGE (NKK*MR)
__device__ __forceinline__ void fma2(u64 &d, u64 a, u64 b){
    asm("fma.rn.f32x2 %0, %1, %2, %0;" : "+l"(d) : "l"(a), "l"(b));
}
__global__ void __launch_bounds__(256)
init_gates(const float* __restrict__ W, const float* __restrict__ Xin,
           const float* __restrict__ bias1, const float* __restrict__ bias2)
{
    extern __shared__ u64 sm[];
    u64* Wb = sm;
    u64* Hb = sm + 2*STAGE;
    const int tid = threadIdx.x;
    const int tv = tid & 15, tb = tid >> 4;
    const int vbase = blockIdx.x * 64;
    const u64* gW = reinterpret_cast<const u64*>(W) + (size_t)vbase * (Hn/2);
    const u64* gX = reinterpret_cast<const u64*>(Xin);
    const int kkc = tid & 31, r0 = tid >> 5;

    u64 acc[4][4];
    #pragma unroll
    for (int i=0;i<4;i++)
        #pragma unroll
        for (int j=0;j<4;j++) acc[i][j]=0ull;

    u64 wreg[8], hreg[8];
    #pragma unroll
    for (int jj=0; jj<8; jj++){
        int row = r0 + 8*jj;
        wreg[jj] = gW[(size_t)row*(Hn/2) + kkc];
        hreg[jj] = gX[(size_t)row*(Hn/2) + kkc];
    }
    #pragma unroll
    for (int jj=0; jj<8; jj++){
        int row = r0 + 8*jj;
        Wb[kkc*MR + row] = wreg[jj];
        Hb[kkc*MR + row] = hreg[jj];
    }
    __syncthreads();

    const int NS = Hn / (NKK*2);
    for (int s=0; s<NS; s++){
        const int buf = s & 1;
        if (s+1 < NS){
            const int ko = (s+1)*NKK;
            #pragma unroll
            for (int jj=0; jj<8; jj++){
                int row = r0 + 8*jj;
                wreg[jj] = gW[(size_t)row*(Hn/2) + ko + kkc];
                hreg[jj] = gX[(size_t)row*(Hn/2) + ko + kkc];
            }
        }
        const u64* wp = Wb + buf*STAGE + tv;
        const u64* hp = Hb + buf*STAGE + tb;
        #pragma unroll
        for (int kk=0; kk<NKK; kk++){
            u64 w2[4], h2[4];
            #pragma unroll
            for (int i=0;i<4;i++) w2[i] = wp[kk*MR + 16*i];
            #pragma unroll
            for (int j=0;j<4;j++) h2[j] = hp[kk*MR + 16*j];
            #pragma unroll
            for (int i=0;i<4;i++)
                #pragma unroll
                for (int j=0;j<4;j++)
                    fma2(acc[i][j], w2[i], h2[j]);
        }
        if (s+1 < NS){
            const int nb = (s+1)&1;
            #pragma unroll
            for (int jj=0; jj<8; jj++){
                int row = r0 + 8*jj;
                Wb[nb*STAGE + kkc*MR + row] = wreg[jj];
                Hb[nb*STAGE + kkc*MR + row] = hreg[jj];
            }
        }
        __syncthreads();
    }
    #pragma unroll
    for (int i=0;i<4;i++){
        int v = vbase + tv + 16*i;
        float bv = bias1[v] + bias2[v];
        #pragma unroll
        for (int j=0;j<4;j++){
            int b = tb + 16*j;
            u64 a = acc[i][j];
            float lo = __uint_as_float((unsigned)a);
            float hi = __uint_as_float((unsigned)(a>>32));
            g_gates[b*G4 + v] = lo + hi + bv;
        }
    }
}

// ---------------- step GEMM: D[v,b] = W_fc @ h^T via bf16x6 mma.sync ----------------
// grid=128 (M=64 v/CTA), 512 thr = 16 warps as 4(M-16)x4(N-16).
// K=1024 in 16 chunks of 64; 4-stage cp.async ring, depth-3 prefetch,
// one barrier per chunk.
// Accumulators split into 3 independent groups (A=a0b0, B=a0b1+a1b0,
// C=a1b1+a0b2+a2b0) -> 6 independent HMMA chains per warp instead of 2;
// summed in the epilogue. Breaks the accumulator-RAW chain that bound R13/R14.
#define ABYTES 8192u                 // one limb-plane chunk: 64 rows x 128B
#define STG_BYTES (6u*ABYTES)        // 3 A limbs + 3 B limbs = 48KB
#define NSTG 4

__global__ void __launch_bounds__(512)
gemm_tc(const float* __restrict__ bfc, float* __restrict__ outp,
        int t, int T, int staged)
{
    extern __shared__ __align__(16) char dyn[];
    const int tid  = threadIdx.x;
    const int lane = tid & 31;
    const int wid  = tid >> 5;
    const int wm   = wid & 3;       // M 16-row slab (0..3)
    const int wn   = wid >> 2;      // N 16-col slab (0..3)
    const int vbase = blockIdx.x * 64;

    const u32 dyn0 = smem_u32(dyn);
    const u32 sb_u = (dyn0 + 1023) & ~1023u;      // 1KB align for SW128
    char* sbp = dyn + (sb_u - dyn0);

    const uint4* gA[3] = {(const uint4*)g_W0, (const uint4*)g_W1, (const uint4*)g_W2};
    const uint4* gB[3] = {(const uint4*)g_h0, (const uint4*)g_h1, (const uint4*)g_h2};

    // staging: 512 threads, each thread owns one row (0..63) and one 16B col (0..7)
    const int c8 = tid & 7, r0 = tid >> 3;

    auto stage_chunk = [&](int kc, int buf){
        const u32 base = sb_u + (u32)buf*STG_BYTES;
        const u32 off = SW128((u32)(r0*128 + c8*16));
        #pragma unroll
        for (int l=0;l<3;l++){
            CP16(base + l*ABYTES + off,
                 (const void*)(gA[l] + (size_t)(vbase+r0)*128 + kc*8 + c8));
            CP16(base + (3+l)*ABYTES + off,
                 (const void*)(gB[l] + (size_t)r0*128 + kc*8 + c8));
        }
        CP_COMMIT();
    };

    // 3 accumulator groups x 2 n-tiles x 4 regs = 6 independent HMMA chains
    float accA[2][4], accB[2][4], accC[2][4];
    #pragma unroll
    for (int j=0;j<2;j++)
        #pragma unroll
        for (int r=0;r<4;r++){ accA[j][r]=0.0f; accB[j][r]=0.0f; accC[j][r]=0.0f; }

    // ldmatrix lane addressing
    // A: x4 -> {rows0-7/k0-7, rows8-15/k0-7, rows0-7/k8-15, rows8-15/k8-15} = a0..a3
    const u32 aRow = (u32)(wm*16 + (lane & 15));
    const u32 aKb  = (u32)((lane >> 4) << 4);
    // B (stored [n][k]): NON-trans x4 -> {b0/nt0, b1/nt0, b0/nt1, b1/nt1}
    const u32 bRow = (u32)(wn*16 + (lane & 7) + ((lane >> 4) << 3));
    const u32 bKb  = (u32)(((lane >> 3) & 1) << 4);

    stage_chunk(0, 0);
    stage_chunk(1, 1);
    stage_chunk(2, 2);

    for (int kc = 0; kc < 16; kc++){
        const int buf = kc & 3;
        if (kc < 14)      { CP_WAIT(2); }
        else if (kc == 14){ CP_WAIT(1); }
        else              { CP_WAIT(0); }
        __syncthreads();
        if (kc+3 < 16) stage_chunk(kc+3, (kc+3)&3);

        const u32 base = sb_u + (u32)buf*STG_BYTES;
        #pragma unroll
        for (int ks=0; ks<4; ks++){
            const u32 koff = (u32)(ks*32);
            u32 afr[3][4], bfr[3][4];
            #pragma unroll
            for (int l=0;l<3;l++)
                LDSM_X4(afr[l], base + l*ABYTES + SW128(aRow*128 + koff + aKb));
            #pragma unroll
            for (int l=0;l<3;l++)
                LDSM_X4(bfr[l], base + (3+l)*ABYTES + SW128(bRow*128 + koff + bKb));

            // group A: a0*b0 (chains accA[0], accA[1])
            MMA16816(accA[0], afr[0], bfr[0][0], bfr[0][1]);
            MMA16816(accA[1], afr[0], bfr[0][2], bfr[0][3]);
            // group B: a0*b1 + a1*b0 (chains accB[0], accB[1])
            MMA16816(accB[0], afr[0], bfr[1][0], bfr[1][1]);
            MMA16816(accB[1], afr[0], bfr[1][2], bfr[1][3]);
            MMA16816(accB[0], afr[1], bfr[0][0], bfr[0][1]);
            MMA16816(accB[1], afr[1], bfr[0][2], bfr[0][3]);
            // group C: a1*b1 + a0*b2 + a2*b0 (chains accC[0], accC[1])
            MMA16816(accC[0], afr[1], bfr[1][0], bfr[1][1]);
            MMA16816(accC[1], afr[1], bfr[1][2], bfr[1][3]);
            MMA16816(accC[0], afr[0], bfr[2][0], bfr[2][1]);
            MMA16816(accC[1], afr[0], bfr[2][2], bfr[2][3]);
            MMA16816(accC[0], afr[2], bfr[0][0], bfr[0][1]);
            MMA16816(accC[1], afr[2], bfr[0][2], bfr[0][3]);
        }
        // no trailing barrier: next iteration's leading barrier protects buffers
    }

    // Epilogue: acc thread map (m16n8): rows lane>>2 (+8), cols (lane&3)*2 (+1)
    float* sv = (float*)sbp;   // reuse buffer 0 region (all warps passed later barriers)
    const int rr = lane >> 2;
    const int cc = (lane & 3) * 2;
    const int vr0 = wm*16 + rr;                  // local v rows vr0, vr0+8
    const float bv0 = bfc[vbase + vr0];
    const float bv1 = bfc[vbase + vr0 + 8];
    #pragma unroll
    for (int nt=0; nt<2; nt++){
        const int b0 = wn*16 + nt*8 + cc;        // cols b0, b0+1
        float x00 = ((accA[nt][0] + accB[nt][0]) + accC[nt][0]) + bv0;
        float x01 = ((accA[nt][1] + accB[nt][1]) + accC[nt][1]) + bv0;
        float x10 = ((accA[nt][2] + accB[nt][2]) + accC[nt][2]) + bv1;
        float x11 = ((accA[nt][3] + accB[nt][3]) + accC[nt][3]) + bv1;
        sv[vr0*65 + b0]       = x00;
        sv[vr0*65 + b0+1]     = x01;
        sv[(vr0+8)*65 + b0]   = x10;
        sv[(vr0+8)*65 + b0+1] = x11;
        if (staged){
            float* sp = g_stage + (size_t)t*Bn*Vn;
            sp[(size_t)b0*Vn     + vbase + vr0]     = x00;
            sp[(size_t)(b0+1)*Vn + vbase + vr0]     = x01;
            sp[(size_t)b0*Vn     + vbase + vr0 + 8] = x10;
            sp[(size_t)(b0+1)*Vn + vbase + vr0 + 8] = x11;
        } else {
            outp[((size_t)b0*Vn     + vbase + vr0)    *(size_t)T + t] = x00;
            outp[((size_t)(b0+1)*Vn + vbase + vr0)    *(size_t)T + t] = x01;
            outp[((size_t)b0*Vn     + vbase + vr0 + 8)*(size_t)T + t] = x10;
            outp[((size_t)(b0+1)*Vn + vbase + vr0 + 8)*(size_t)T + t] = x11;
        }
    }
    __syncthreads();
    // Per-CTA argmax over local 64 v for each b. Tie -> lowest v.
    if (tid < Bn){
        float best = sv[tid]; int bi = 0;
        #pragma unroll 4
        for (int vv=1; vv<64; vv++){
            float x = sv[vv*65 + tid];
            if (x > best){ best = x; bi = vv; }
        }
        g_pval[tid*NPART + blockIdx.x] = best;
        g_pidx[tid*NPART + blockIdx.x] = vbase + bi;
    }
}

// ---------------- per-step cell (grid = 128: 2 CTAs per batch row, 512 thr) ----------------
__global__ void __launch_bounds__(512)
cell_kernel(int t)
{
    const int b    = blockIdx.x >> 1;
    const int half = blockIdx.x & 1;
    const int tid  = threadIdx.x;
    __shared__ int s_idx;

    if (t > 0){
        if (tid < 32){
            float bv = g_pval[b*NPART + tid];
            int   bi = g_pidx[b*NPART + tid];
            #pragma unroll
            for (int j=1;j<4;j++){
                float v2 = g_pval[b*NPART + tid + 32*j];
                int   i2 = g_pidx[b*NPART + tid + 32*j];
                if (v2 > bv || (v2 == bv && i2 < bi)){ bv=v2; bi=i2; }
            }
            #pragma unroll
            for (int s=16;s>0;s>>=1){
                float v2 = __shfl_xor_sync(0xffffffffu, bv, s);
                int   i2 = __shfl_xor_sync(0xffffffffu, bi, s);
                if (v2 > bv || (v2 == bv && i2 < bi)){ bv=v2; bi=i2; }
            }
            if (tid == 0) s_idx = bi;
        }
        __syncthreads();
        const int h = half*512 + tid;
        const float* __restrict__ col = g_WihT + (size_t)s_idx * G4;
        float ig = g_gates[b*G4 + h]        + col[h];
        float fg = g_gates[b*G4 + Hn + h]   + col[Hn + h];
        float gg = g_gates[b*G4 + 2*Hn + h] + col[2*Hn + h];
        float og = g_gates[b*G4 + 3*Hn + h] + col[3*Hn + h];
        g_gates[b*G4 + h]        = ig;
        g_gates[b*G4 + Hn + h]   = fg;
        g_gates[b*G4 + 2*Hn + h] = gg;
        g_gates[b*G4 + 3*Hn + h] = og;
        float c0 = g_c[b*Hn + h];
        float c  = sigm(fg)*c0 + sigm(ig)*tanhf(gg);
        g_c[b*Hn + h] = c;
        float hv = sigm(og)*tanhf(c);
        __nv_bfloat16 l0 = __float2bfloat16(hv);
        float r = hv - __bfloat162float(l0);
        __nv_bfloat16 l1 = __float2bfloat16(r);
        r -= __bfloat162float(l1);
        __nv_bfloat16 l2 = __float2bfloat16(r);
        g_h0[b*Hn + h] = l0;
        g_h1[b*Hn + h] = l1;
        g_h2[b*Hn + h] = l2;
    } else {
        const int h = half*512 + tid;
        float ig = g_gates[b*G4 + h];
        float gg = g_gates[b*G4 + 2*Hn + h];
        float og = g_gates[b*G4 + 3*Hn + h];
        float c  = sigm(ig)*tanhf(gg);           // c0 = 0
        g_c[b*Hn + h] = c;
        float hv = sigm(og)*tanhf(c);
        __nv_bfloat16 l0 = __float2bfloat16(hv);
        float r = hv - __bfloat162float(l0);
        __nv_bfloat16 l1 = __float2bfloat16(r);
        r -= __bfloat162float(l1);
        __nv_bfloat16 l2 = __float2bfloat16(r);
        g_h0[b*Hn + h] = l0;
        g_h1[b*Hn + h] = l1;
        g_h2[b*Hn + h] = l2;
    }
}

// ---------------- g_stage[t][b][v] -> out[b][v][t] ----------------
__global__ void __launch_bounds__(256)
out_transpose(float* __restrict__ out, int T)
{
    __shared__ float tile[32][33];
    const int b  = blockIdx.z;
    const int v0 = blockIdx.x * 32;
    const int t0 = blockIdx.y * 32;
    const int tx = threadIdx.x, ty = threadIdx.y;
    #pragma unroll
    for (int i = 0; i < 32; i += 8)
        tile[ty+i][tx] = g_stage[((size_t)(t0+ty+i)*Bn + b)*(size_t)Vn + (v0+tx)];
    __syncthreads();
    #pragma unroll
    for (int i = 0; i < 32; i += 8)
        out[((size_t)b*Vn + (v0+ty+i))*(size_t)T + (t0+tx)] = tile[tx][ty+i];
}

// ---------------------------------------------------------------------------
extern "C" void kernel_launch(void* const* d_in, const int* in_sizes, int n_in,
                              void* d_out, int out_size)
{
    const float* h0   = (const float*)d_in[0];
    const float* W_ih = (const float*)d_in[1];
    const float* W_hh = (const float*)d_in[2];
    const float* b_ih = (const float*)d_in[3];
    const float* b_hh = (const float*)d_in[4];
    const float* W_fc = (const float*)d_in[5];
    const float* b_fc = (const float*)d_in[6];
    float* out = (float*)d_out;

    const int T = out_size / (Bn * Vn);
    const int staged = (T <= TMAX && (T % 32) == 0) ? 1 : 0;

    const int smem_init = (int)(4 * STAGE * sizeof(u64));       // 66,560
    const int smem_tc   = (int)(1024 + NSTG * STG_BYTES);       // 197,632
    cudaFuncSetAttribute(init_gates, cudaFuncAttributeMaxDynamicSharedMemorySize, smem_init);
    cudaFuncSetAttribute(gemm_tc,    cudaFuncAttributeMaxDynamicSharedMemorySize, smem_tc);

    // launch 0: merged prep (W_ih transpose + W_fc limb split)
    prep_weights<<<SPLIT_BLOCKS + (Vn/32)*(G4/32), 256>>>(W_ih, W_fc);
    // launch 1: init gates
    init_gates<<<G4/64, 256, smem_init>>>(W_hh, h0, b_ih, b_hh);

    // launches 2,3,...: cell, gemm per step (gemm_tc t=0 = launch index 3 = ncu slot)
    for (int t = 0; t < T; t++){
        cell_kernel<<<2*Bn, 512>>>(t);
        gemm_tc<<<NPART, 512, smem_tc>>>(b_fc, out, t, T, staged);
    }

    if (staged)
        out_transpose<<<dim3(Vn/32, T/32, Bn), dim3(32,8)>>>(out, T);
}

// round 16
// speedup vs baseline: 1.0415x; 1.0415x over previous
#include <cuda_runtime.h>
#include <cuda_bf16.h>
#include <cstdint>
#include <cstddef>
#include <math.h>

// Problem constants
#define Bn 64
#define Hn 1024
#define Vn 8192
#define G4 4096
#define TMAX 128
#define NPART 128          // step-gemm grid = 128 v-tiles of 64

typedef unsigned long long u64;
typedef unsigned int u32;

// ---------------- persistent device state (legal scratch) ----------------
__device__ __align__(128) float g_gates[Bn*G4];
__device__ __align__(128) float g_c[Bn*Hn];
__device__ float g_pval[Bn*NPART];
__device__ int   g_pidx[Bn*NPART];
__device__ __align__(128) float g_WihT[(size_t)Vn*G4];        // W_ih^T for coalesced column gather
__device__ __align__(128) float g_stage[(size_t)TMAX*Bn*Vn];  // step outputs, t-major
// bf16x3 limbs of W_fc (V x H each) and of h (B x H each)
__device__ __align__(128) __nv_bfloat16 g_W0[(size_t)Vn*Hn];
__device__ __align__(128) __nv_bfloat16 g_W1[(size_t)Vn*Hn];
__device__ __align__(128) __nv_bfloat16 g_W2[(size_t)Vn*Hn];
__device__ __align__(128) __nv_bfloat16 g_h0[Bn*Hn];
__device__ __align__(128) __nv_bfloat16 g_h1[Bn*Hn];
__device__ __align__(128) __nv_bfloat16 g_h2[Bn*Hn];

__device__ __forceinline__ float sigm(float x){ return 1.0f/(1.0f+expf(-x)); }

__device__ __forceinline__ u32 smem_u32(const void* p){
    u32 a;
    asm("{ .reg .u64 t; cvta.to.shared.u64 t, %1; cvt.u32.u64 %0, t; }" : "=r"(a) : "l"(p));
    return a;
}
#define SW128(o) ((o) ^ (((o)>>3)&0x70))

// ---- baseline-PTX ops (all sm_80-era: safe on compute_103) ----
#define LDSM_X4(r, a) \
    asm volatile("ldmatrix.sync.aligned.m8n8.x4.shared.b16 {%0,%1,%2,%3}, [%4];" \
        : "=r"((r)[0]),"=r"((r)[1]),"=r"((r)[2]),"=r"((r)[3]) : "r"(a))
#define MMA16816(d, a, b0v, b1v) \
    asm volatile("mma.sync.aligned.m16n8k16.row.col.f32.bf16.bf16.f32 " \
        "{%0,%1,%2,%3}, {%4,%5,%6,%7}, {%8,%9}, {%0,%1,%2,%3};" \
        : "+f"((d)[0]),"+f"((d)[1]),"+f"((d)[2]),"+f"((d)[3]) \
        : "r"((a)[0]),"r"((a)[1]),"r"((a)[2]),"r"((a)[3]), "r"(b0v),"r"(b1v))
#define CP16(dst, src) \
    asm volatile("cp.async.cg.shared.global [%0], [%1], 16;" :: "r"(dst), "l"(src))
#define CP_COMMIT() asm volatile("cp.async.commit_group;" ::: "memory")
#define CP_WAIT(N)  asm volatile("cp.async.wait_group %0;" :: "n"(N) : "memory")
#define BARH(id) asm volatile("bar.sync %0, 256;" :: "r"(id) : "memory")

// ---------------- one-time prep: W_ih transpose + W_fc limb split ----------------
#define SPLIT_BLOCKS 8192
__global__ void __launch_bounds__(256)
prep_weights(const float* __restrict__ Wih, const float* __restrict__ Wfc)
{
    if (blockIdx.x < SPLIT_BLOCKS){
        // W_fc (fp32) -> 3 bf16 limbs, 4 floats/thread
        size_t base = ((size_t)blockIdx.x*256 + threadIdx.x)*4;
        float4 a = *(const float4*)(Wfc + base);
        float v[4] = {a.x, a.y, a.z, a.w};
        unsigned short p0[4], p1[4], p2[4];
        #pragma unroll
        for (int i=0;i<4;i++){
            __nv_bfloat16 b0 = __float2bfloat16(v[i]);
            float r = v[i] - __bfloat162float(b0);
            __nv_bfloat16 b1 = __float2bfloat16(r);
            r -= __bfloat162float(b1);
            __nv_bfloat16 b2 = __float2bfloat16(r);
            p0[i] = *(unsigned short*)&b0;
            p1[i] = *(unsigned short*)&b1;
            p2[i] = *(unsigned short*)&b2;
        }
        u64 w0 = (u64)p0[0] | ((u64)p0[1]<<16) | ((u64)p0[2]<<32) | ((u64)p0[3]<<48);
        u64 w1 = (u64)p1[0] | ((u64)p1[1]<<16) | ((u64)p1[2]<<32) | ((u64)p1[3]<<48);
        u64 w2 = (u64)p2[0] | ((u64)p2[1]<<16) | ((u64)p2[2]<<32) | ((u64)p2[3]<<48);
        ((u64*)g_W0)[base/4] = w0;
        ((u64*)g_W1)[base/4] = w1;
        ((u64*)g_W2)[base/4] = w2;
    } else {
        // W_ih (4H x V) -> g_WihT (V x 4H), tiled transpose
        __shared__ float tile[32][33];
        const int bx = blockIdx.x - SPLIT_BLOCKS;
        const int v0 = (bx & 255) * 32;       // 256 v-tiles
        const int g0 = (bx >> 8) * 32;        // 128 g-tiles
        const int tx = threadIdx.x & 31, ty = threadIdx.x >> 5;   // 32 x 8
        #pragma unroll
        for (int i = 0; i < 32; i += 8)
            tile[ty+i][tx] = Wih[(size_t)(g0+ty+i)*Vn + (v0+tx)];
        __syncthreads();
        #pragma unroll
        for (int i = 0; i < 32; i += 8)
            g_WihT[(size_t)(v0+ty+i)*G4 + (g0+tx)] = tile[tx][ty+i];
    }
}

// ---------------- init: gates0 = h0 @ W_hh^T + b_ih + b_hh (SIMT, runs once) ----------------
#define NKK 32
#define MR  65
#define STAGE (NKK*MR)
__device__ __forceinline__ void fma2(u64 &d, u64 a, u64 b){
    asm("fma.rn.f32x2 %0, %1, %2, %0;" : "+l"(d) : "l"(a), "l"(b));
}
__global__ void __launch_bounds__(256)
init_gates(const float* __restrict__ W, const float* __restrict__ Xin,
           const float* __restrict__ bias1, const float* __restrict__ bias2)
{
    extern __shared__ u64 sm[];
    u64* Wb = sm;
    u64* Hb = sm + 2*STAGE;
    const int tid = threadIdx.x;
    const int tv = tid & 15, tb = tid >> 4;
    const int vbase = blockIdx.x * 64;
    const u64* gW = reinterpret_cast<const u64*>(W) + (size_t)vbase * (Hn/2);
    const u64* gX = reinterpret_cast<const u64*>(Xin);
    const int kkc = tid & 31, r0 = tid >> 5;

    u64 acc[4][4];
    #pragma unroll
    for (int i=0;i<4;i++)
        #pragma unroll
        for (int j=0;j<4;j++) acc[i][j]=0ull;

    u64 wreg[8], hreg[8];
    #pragma unroll
    for (int jj=0; jj<8; jj++){
        int row = r0 + 8*jj;
        wreg[jj] = gW[(size_t)row*(Hn/2) + kkc];
        hreg[jj] = gX[(size_t)row*(Hn/2) + kkc];
    }
    #pragma unroll
    for (int jj=0; jj<8; jj++){
        int row = r0 + 8*jj;
        Wb[kkc*MR + row] = wreg[jj];
        Hb[kkc*MR + row] = hreg[jj];
    }
    __syncthreads();

    const int NS = Hn / (NKK*2);
    for (int s=0; s<NS; s++){
        const int buf = s & 1;
        if (s+1 < NS){
            const int ko = (s+1)*NKK;
            #pragma unroll
            for (int jj=0; jj<8; jj++){
                int row = r0 + 8*jj;
                wreg[jj] = gW[(size_t)row*(Hn/2) + ko + kkc];
                hreg[jj] = gX[(size_t)row*(Hn/2) + ko + kkc];
            }
        }
        const u64* wp = Wb + buf*STAGE + tv;
        const u64* hp = Hb + buf*STAGE + tb;
        #pragma unroll
        for (int kk=0; kk<NKK; kk++){
            u64 w2[4], h2[4];
            #pragma unroll
            for (int i=0;i<4;i++) w2[i] = wp[kk*MR + 16*i];
            #pragma unroll
            for (int j=0;j<4;j++) h2[j] = hp[kk*MR + 16*j];
            #pragma unroll
            for (int i=0;i<4;i++)
                #pragma unroll
                for (int j=0;j<4;j++)
                    fma2(acc[i][j], w2[i], h2[j]);
        }
        if (s+1 < NS){
            const int nb = (s+1)&1;
            #pragma unroll
            for (int jj=0; jj<8; jj++){
                int row = r0 + 8*jj;
                Wb[nb*STAGE + kkc*MR + row] = wreg[jj];
                Hb[nb*STAGE + kkc*MR + row] = hreg[jj];
            }
        }
        __syncthreads();
    }
    #pragma unroll
    for (int i=0;i<4;i++){
        int v = vbase + tv + 16*i;
        float bv = bias1[v] + bias2[v];
        #pragma unroll
        for (int j=0;j<4;j++){
            int b = tb + 16*j;
            u64 a = acc[i][j];
            float lo = __uint_as_float((unsigned)a);
            float hi = __uint_as_float((unsigned)(a>>32));
            g_gates[b*G4 + v] = lo + hi + bv;
        }
    }
}

// ---------------- step GEMM: D[v,b] = W_fc @ h^T via bf16x6 mma.sync ----------------
// grid=128 (M=64 v/CTA), 512 thr = 16 warps in TWO INDEPENDENT K-HALVES:
//   warps 0-7  : even K-chunks, own 2-stage cp.async ring, named barrier 1
//   warps 8-15 : odd  K-chunks, own 2-stage cp.async ring, named barrier 2
// Each half: 8 warps as 4(M-16) x 2(N-32). Partial sums combined via smem.
// Decouples the whole-SM CP_WAIT/barrier stall that bound R13-R15.
#define ABYTES 8192u                 // one limb-plane chunk: 64 rows x 128B
#define STG_BYTES (6u*ABYTES)        // 3 A limbs + 3 B limbs = 48KB

__global__ void __launch_bounds__(512)
gemm_tc(const float* __restrict__ bfc, float* __restrict__ outp,
        int t, int T, int staged)
{
    extern __shared__ __align__(16) char dyn[];
    const int tid  = threadIdx.x;
    const int lane = tid & 31;
    const int wid  = tid >> 5;
    const int half = wid >> 3;       // 0 or 1 (K-split)
    const int hw   = wid & 7;
    const int wm   = hw & 3;         // M 16-row slab (0..3)
    const int wn   = hw >> 2;        // N 32-col slab (0..1)
    const int vbase = blockIdx.x * 64;

    const u32 dyn0 = smem_u32(dyn);
    const u32 sb_u = (dyn0 + 1023) & ~1023u;      // 1KB align for SW128
    char* sbp = dyn + (sb_u - dyn0);
    const u32 ring = sb_u + (u32)half * 2u * STG_BYTES;

    const uint4* gA[3] = {(const uint4*)g_W0, (const uint4*)g_W1, (const uint4*)g_W2};
    const uint4* gB[3] = {(const uint4*)g_h0, (const uint4*)g_h1, (const uint4*)g_h2};

    // per-half staging: 256 threads, each owns 2 rows x one 16B col
    const int htid = tid & 255;
    const int c8 = htid & 7, r2 = htid >> 3;      // rows r2, r2+32

    auto stage_chunk = [&](int kc, int s){
        const u32 base = ring + (u32)s*STG_BYTES;
        #pragma unroll
        for (int j=0;j<2;j++){
            int row = r2 + 32*j;
            u32 off = SW128((u32)(row*128 + c8*16));
            #pragma unroll
            for (int l=0;l<3;l++){
                CP16(base + l*ABYTES + off,
                     (const void*)(gA[l] + (size_t)(vbase+row)*128 + kc*8 + c8));
                CP16(base + (3+l)*ABYTES + off,
                     (const void*)(gB[l] + (size_t)row*128 + kc*8 + c8));
            }
        }
        CP_COMMIT();
    };

    // 3 accumulator groups x 4 n8-tiles = 12 independent HMMA chains per warp
    float accA[4][4], accB[4][4], accC[4][4];
    #pragma unroll
    for (int j=0;j<4;j++)
        #pragma unroll
        for (int r=0;r<4;r++){ accA[j][r]=0.0f; accB[j][r]=0.0f; accC[j][r]=0.0f; }

    // ldmatrix lane addressing
    const u32 aRow = (u32)(wm*16 + (lane & 15));
    const u32 aKb  = (u32)((lane >> 4) << 4);
    const u32 bR0  = (u32)(wn*32 + (lane & 7) + ((lane >> 4) << 3));
    const u32 bKb  = (u32)(((lane >> 3) & 1) << 4);

    // half's chunks: kc = 2*i + half, i = 0..7
    stage_chunk(half, 0);
    stage_chunk(2 + half, 1);

    #pragma unroll 1
    for (int i = 0; i < 8; i++){
        if (i < 7) { CP_WAIT(1); } else { CP_WAIT(0); }
        BARH(1 + half);
        const u32 base = ring + (u32)(i & 1)*STG_BYTES;
        #pragma unroll
        for (int ks=0; ks<4; ks++){
            const u32 koff = (u32)(ks*32);
            u32 afr[3][4], bfr[3][2][4];
            #pragma unroll
            for (int l=0;l<3;l++)
                LDSM_X4(afr[l], base + l*ABYTES + SW128(aRow*128 + koff + aKb));
            #pragma unroll
            for (int l=0;l<3;l++)
                #pragma unroll
                for (int ng=0; ng<2; ng++)
                    LDSM_X4(bfr[l][ng], base + (3+l)*ABYTES +
                            SW128((bR0 + (u32)(ng*16))*128 + koff + bKb));
            #pragma unroll
            for (int j=0;j<4;j++){
                const int ng = j >> 1, rb = (j & 1)*2;
                MMA16816(accA[j], afr[0], bfr[0][ng][rb], bfr[0][ng][rb+1]);
                MMA16816(accB[j], afr[0], bfr[1][ng][rb], bfr[1][ng][rb+1]);
                MMA16816(accB[j], afr[1], bfr[0][ng][rb], bfr[0][ng][rb+1]);
                MMA16816(accC[j], afr[1], bfr[1][ng][rb], bfr[1][ng][rb+1]);
                MMA16816(accC[j], afr[0], bfr[2][ng][rb], bfr[2][ng][rb+1]);
                MMA16816(accC[j], afr[2], bfr[0][ng][rb], bfr[0][ng][rb+1]);
            }
        }
        BARH(1 + half);                               // all half-warps done reading stage i&1
        if (i + 2 < 8) stage_chunk(2*(i+2) + half, i & 1);
    }

    // ---- combine halves + epilogue ----
    __syncthreads();                  // both halves done; rings reusable
    float* sp = (float*)sbp;          // 64 x 65 partial/result tile
    const int rr = lane >> 2;
    const int cc = (lane & 3) * 2;
    const int vr0 = wm*16 + rr;       // local v rows vr0, vr0+8

    if (half == 1){
        #pragma unroll
        for (int j=0;j<4;j++){
            const int b0 = wn*32 + j*8 + cc;
            sp[vr0*65 + b0]       = (accA[j][0]+accB[j][0])+accC[j][0];
            sp[vr0*65 + b0+1]     = (accA[j][1]+accB[j][1])+accC[j][1];
            sp[(vr0+8)*65 + b0]   = (accA[j][2]+accB[j][2])+accC[j][2];
            sp[(vr0+8)*65 + b0+1] = (accA[j][3]+accB[j][3])+accC[j][3];
        }
    }
    __syncthreads();
    if (half == 0){
        const float bv0 = bfc[vbase + vr0];
        const float bv1 = bfc[vbase + vr0 + 8];
        float* spt = staged ? (g_stage + (size_t)t*Bn*Vn) : nullptr;
        #pragma unroll
        for (int j=0;j<4;j++){
            const int b0 = wn*32 + j*8 + cc;
            float x00 = (((accA[j][0]+accB[j][0])+accC[j][0]) + sp[vr0*65 + b0])       + bv0;
            float x01 = (((accA[j][1]+accB[j][1])+accC[j][1]) + sp[vr0*65 + b0+1])     + bv0;
            float x10 = (((accA[j][2]+accB[j][2])+accC[j][2]) + sp[(vr0+8)*65 + b0])   + bv1;
            float x11 = (((accA[j][3]+accB[j][3])+accC[j][3]) + sp[(vr0+8)*65 + b0+1]) + bv1;
            sp[vr0*65 + b0]       = x00;
            sp[vr0*65 + b0+1]     = x01;
            sp[(vr0+8)*65 + b0]   = x10;
            sp[(vr0+8)*65 + b0+1] = x11;
            if (staged){
                spt[(size_t)b0*Vn     + vbase + vr0]     = x00;
                spt[(size_t)(b0+1)*Vn + vbase + vr0]     = x01;
                spt[(size_t)b0*Vn     + vbase + vr0 + 8] = x10;
                spt[(size_t)(b0+1)*Vn + vbase + vr0 + 8] = x11;
            } else {
                outp[((size_t)b0*Vn     + vbase + vr0)    *(size_t)T + t] = x00;
                outp[((size_t)(b0+1)*Vn + vbase + vr0)    *(size_t)T + t] = x01;
                outp[((size_t)b0*Vn     + vbase + vr0 + 8)*(size_t)T + t] = x10;
                outp[((size_t)(b0+1)*Vn + vbase + vr0 + 8)*(size_t)T + t] = x11;
            }
        }
    }
    __syncthreads();
    // Per-CTA argmax over local 64 v for each b. Tie -> lowest v.
    if (tid < Bn){
        float best = sp[tid]; int bi = 0;
        #pragma unroll 4
        for (int vv=1; vv<64; vv++){
            float x = sp[vv*65 + tid];
            if (x > best){ best = x; bi = vv; }
        }
        g_pval[tid*NPART + blockIdx.x] = best;
        g_pidx[tid*NPART + blockIdx.x] = vbase + bi;
    }
}

// ---------------- per-step cell (grid = 128: 2 CTAs per batch row, 512 thr) ----------------
__global__ void __launch_bounds__(512)
cell_kernel(int t)
{
    const int b    = blockIdx.x >> 1;
    const int half = blockIdx.x & 1;
    const int tid  = threadIdx.x;
    __shared__ int s_idx;

    if (t > 0){
        if (tid < 32){
            float bv = g_pval[b*NPART + tid];
            int   bi = g_pidx[b*NPART + tid];
            #pragma unroll
            for (int j=1;j<4;j++){
                float v2 = g_pval[b*NPART + tid + 32*j];
                int   i2 = g_pidx[b*NPART + tid + 32*j];
                if (v2 > bv || (v2 == bv && i2 < bi)){ bv=v2; bi=i2; }
            }
            #pragma unroll
            for (int s=16;s>0;s>>=1){
                float v2 = __shfl_xor_sync(0xffffffffu, bv, s);
                int   i2 = __shfl_xor_sync(0xffffffffu, bi, s);
                if (v2 > bv || (v2 == bv && i2 < bi)){ bv=v2; bi=i2; }
            }
            if (tid == 0) s_idx = bi;
        }
        __syncthreads();
        const int h = half*512 + tid;
        const float* __restrict__ col = g_WihT + (size_t)s_idx * G4;
        float ig = g_gates[b*G4 + h]        + col[h];
        float fg = g_gates[b*G4 + Hn + h]   + col[Hn + h];
        float gg = g_gates[b*G4 + 2*Hn + h] + col[2*Hn + h];
        float og = g_gates[b*G4 + 3*Hn + h] + col[3*Hn + h];
        g_gates[b*G4 + h]        = ig;
        g_gates[b*G4 + Hn + h]   = fg;
        g_gates[b*G4 + 2*Hn + h] = gg;
        g_gates[b*G4 + 3*Hn + h] = og;
        float c0 = g_c[b*Hn + h];
        float c  = sigm(fg)*c0 + sigm(ig)*tanhf(gg);
        g_c[b*Hn + h] = c;
        float hv = sigm(og)*tanhf(c);
        __nv_bfloat16 l0 = __float2bfloat16(hv);
        float r = hv - __bfloat162float(l0);
        __nv_bfloat16 l1 = __float2bfloat16(r);
        r -= __bfloat162float(l1);
        __nv_bfloat16 l2 = __float2bfloat16(r);
        g_h0[b*Hn + h] = l0;
        g_h1[b*Hn + h] = l1;
        g_h2[b*Hn + h] = l2;
    } else {
        const int h = half*512 + tid;
        float ig = g_gates[b*G4 + h];
        float gg = g_gates[b*G4 + 2*Hn + h];
        float og = g_gates[b*G4 + 3*Hn + h];
        float c  = sigm(ig)*tanhf(gg);           // c0 = 0
        g_c[b*Hn + h] = c;
        float hv = sigm(og)*tanhf(c);
        __nv_bfloat16 l0 = __float2bfloat16(hv);
        float r = hv - __bfloat162float(l0);
        __nv_bfloat16 l1 = __float2bfloat16(r);
        r -= __bfloat162float(l1);
        __nv_bfloat16 l2 = __float2bfloat16(r);
        g_h0[b*Hn + h] = l0;
        g_h1[b*Hn + h] = l1;
        g_h2[b*Hn + h] = l2;
    }
}

// ---------------- g_stage[t][b][v] -> out[b][v][t] ----------------
__global__ void __launch_bounds__(256)
out_transpose(float* __restrict__ out, int T)
{
    __shared__ float tile[32][33];
    const int b  = blockIdx.z;
    const int v0 = blockIdx.x * 32;
    const int t0 = blockIdx.y * 32;
    const int tx = threadIdx.x, ty = threadIdx.y;
    #pragma unroll
    for (int i = 0; i < 32; i += 8)
        tile[ty+i][tx] = g_stage[((size_t)(t0+ty+i)*Bn + b)*(size_t)Vn + (v0+tx)];
    __syncthreads();
    #pragma unroll
    for (int i = 0; i < 32; i += 8)
        out[((size_t)b*Vn + (v0+ty+i))*(size_t)T + (t0+tx)] = tile[tx][ty+i];
}

// ---------------------------------------------------------------------------
extern "C" void kernel_launch(void* const* d_in, const int* in_sizes, int n_in,
                              void* d_out, int out_size)
{
    const float* h0   = (const float*)d_in[0];
    const float* W_ih = (const float*)d_in[1];
    const float* W_hh = (const float*)d_in[2];
    const float* b_ih = (const float*)d_in[3];
    const float* b_hh = (const float*)d_in[4];
    const float* W_fc = (const float*)d_in[5];
    const float* b_fc = (const float*)d_in[6];
    float* out = (float*)d_out;

    const int T = out_size / (Bn * Vn);
    const int staged = (T <= TMAX && (T % 32) == 0) ? 1 : 0;

    const int smem_init = (int)(4 * STAGE * sizeof(u64));       // 66,560
    const int smem_tc   = (int)(1024 + 4 * STG_BYTES);          // 197,632
    cudaFuncSetAttribute(init_gates, cudaFuncAttributeMaxDynamicSharedMemorySize, smem_init);
    cudaFuncSetAttribute(gemm_tc,    cudaFuncAttributeMaxDynamicSharedMemorySize, smem_tc);

    // launch 0: merged prep (W_ih transpose + W_fc limb split)
    prep_weights<<<SPLIT_BLOCKS + (Vn/32)*(G4/32), 256>>>(W_ih, W_fc);
    // launch 1: init gates
    init_gates<<<G4/64, 256, smem_init>>>(W_hh, h0, b_ih, b_hh);

    // launches 2,3,...: cell, gemm per step (gemm_tc t=0 = launch index 3 = ncu slot)
    for (int t = 0; t < T; t++){
        cell_kernel<<<2*Bn, 512>>>(t);
        gemm_tc<<<NPART, 512, smem_tc>>>(b_fc, out, t, T, staged);
    }

    if (staged)
        out_transpose<<<dim3(Vn/32, T/32, Bn), dim3(32,8)>>>(out, T);
}